// round 1
// baseline (speedup 1.0000x reference)
#include <cuda_runtime.h>

#define BB 8
#define N0 4096
#define CIN 1024
#define CC 512
#define NC 4097
#define NP 4352
#define PADF 255
#define NH 8
#define DH 64
#define MLM 256
#define LLM 17
#define BH 64   /* BB*NH */

// ---------------- scratch (device globals; no allocations allowed) ------------
__device__ float g_h0[BB * N0 * CC];            // fc1 output        [8,4096,512]
__device__ float g_h[BB * NC * CC];             // token stream      [8,4097,512]
__device__ float g_xln[BB * NC * CC];
__device__ float g_qkvbuf[BB * NC * 3 * CC];    // [8,4097,1536]
__device__ float g_q[BH * NP * DH];
__device__ float g_k[BH * NP * DH];
__device__ float g_v[BH * NP * DH];
__device__ float g_ql[BH * MLM * DH];
__device__ float g_kl[BH * MLM * DH];
__device__ float g_a1[BH * NP * MLM];           // 285MB
__device__ float g_a3[BH * MLM * NP];           // 285MB
__device__ float g_a2[BH * MLM * MLM];
__device__ float g_z[BH * MLM * MLM];
__device__ float g_z2[BH * MLM * MLM];
__device__ float g_xz[BH * MLM * MLM];
__device__ float g_t[BH * MLM * MLM];
__device__ float g_av[BH * MLM * DH];
__device__ float g_w[BH * NP * MLM];            // 285MB
__device__ float g_ao[BH * NP * DH];
__device__ float g_oflat[BB * NC * CC];
__device__ float g_cls[BB * CC];
__device__ float g_scal[2];

// ---------------- generic GEMM: C = A[MxK] @ B[KxN] (+bias)(+residual)(relu) --
#define GT 64
#define GK 16
__global__ __launch_bounds__(256)
void gemm_kernel(const float* __restrict__ A, const float* __restrict__ B,
                 float* __restrict__ C, int M, int N, int K,
                 const float* __restrict__ bias, const float* __restrict__ residual,
                 int relu)
{
    __shared__ float As[GK][GT + 1];
    __shared__ float Bs[GK][GT + 1];
    int tx = threadIdx.x, ty = threadIdx.y;
    int tid = ty * 16 + tx;
    int row0 = blockIdx.y * GT;
    int col0 = blockIdx.x * GT;
    float acc[4][4] = {};
    for (int k0 = 0; k0 < K; k0 += GK) {
#pragma unroll
        for (int i = 0; i < 4; i++) {
            int idx = tid + i * 256;
            int m = idx >> 4, kk = idx & 15;
            int gm = row0 + m, gk = k0 + kk;
            As[kk][m] = (gm < M && gk < K) ? A[(long)gm * K + gk] : 0.f;
        }
#pragma unroll
        for (int i = 0; i < 4; i++) {
            int idx = tid + i * 256;
            int kk = idx >> 6, n = idx & 63;
            int gk = k0 + kk, gn = col0 + n;
            Bs[kk][n] = (gk < K && gn < N) ? B[(long)gk * N + gn] : 0.f;
        }
        __syncthreads();
#pragma unroll
        for (int kk = 0; kk < GK; kk++) {
            float a[4], b[4];
#pragma unroll
            for (int i = 0; i < 4; i++) a[i] = As[kk][ty * 4 + i];
#pragma unroll
            for (int j = 0; j < 4; j++) b[j] = Bs[kk][tx * 4 + j];
#pragma unroll
            for (int i = 0; i < 4; i++)
#pragma unroll
                for (int j = 0; j < 4; j++) acc[i][j] += a[i] * b[j];
        }
        __syncthreads();
    }
#pragma unroll
    for (int i = 0; i < 4; i++) {
        int gm = row0 + ty * 4 + i;
        if (gm >= M) continue;
#pragma unroll
        for (int j = 0; j < 4; j++) {
            int gn = col0 + tx * 4 + j;
            if (gn >= N) continue;
            float vv = acc[i][j];
            if (bias) vv += bias[gn];
            if (residual) vv += residual[(long)gm * N + gn];
            if (relu) vv = fmaxf(vv, 0.f);
            C[(long)gm * N + gn] = vv;
        }
    }
}

// ---------------- strided-batched GEMM; TB=1 means B is [N,K] (C=A@B^T) ------
template <int TB>
__global__ __launch_bounds__(256)
void bgemm_kernel(const float* __restrict__ A, const float* __restrict__ Bm,
                  float* __restrict__ C, int M, int N, int K,
                  long sA, long sB, long sC, float alpha)
{
    const float* Ab = A + (long)blockIdx.z * sA;
    const float* Bb = Bm + (long)blockIdx.z * sB;
    float* Cb = C + (long)blockIdx.z * sC;
    __shared__ float As[GK][GT + 1];
    __shared__ float Bs[GK][GT + 1];
    int tx = threadIdx.x, ty = threadIdx.y;
    int tid = ty * 16 + tx;
    int row0 = blockIdx.y * GT;
    int col0 = blockIdx.x * GT;
    float acc[4][4] = {};
    for (int k0 = 0; k0 < K; k0 += GK) {
#pragma unroll
        for (int i = 0; i < 4; i++) {
            int idx = tid + i * 256;
            int m = idx >> 4, kk = idx & 15;
            int gm = row0 + m, gk = k0 + kk;
            As[kk][m] = (gm < M && gk < K) ? Ab[(long)gm * K + gk] : 0.f;
        }
#pragma unroll
        for (int i = 0; i < 4; i++) {
            int idx = tid + i * 256;
            if (TB) {
                int n = idx >> 4, kk = idx & 15;
                int gn = col0 + n, gk = k0 + kk;
                Bs[kk][n] = (gn < N && gk < K) ? Bb[(long)gn * K + gk] : 0.f;
            } else {
                int kk = idx >> 6, n = idx & 63;
                int gk = k0 + kk, gn = col0 + n;
                Bs[kk][n] = (gk < K && gn < N) ? Bb[(long)gk * N + gn] : 0.f;
            }
        }
        __syncthreads();
#pragma unroll
        for (int kk = 0; kk < GK; kk++) {
            float a[4], b[4];
#pragma unroll
            for (int i = 0; i < 4; i++) a[i] = As[kk][ty * 4 + i];
#pragma unroll
            for (int j = 0; j < 4; j++) b[j] = Bs[kk][tx * 4 + j];
#pragma unroll
            for (int i = 0; i < 4; i++)
#pragma unroll
                for (int j = 0; j < 4; j++) acc[i][j] += a[i] * b[j];
        }
        __syncthreads();
    }
#pragma unroll
    for (int i = 0; i < 4; i++) {
        int gm = row0 + ty * 4 + i;
        if (gm >= M) continue;
#pragma unroll
        for (int j = 0; j < 4; j++) {
            int gn = col0 + tx * 4 + j;
            if (gn >= N) continue;
            Cb[(long)gm * N + gn] = alpha * acc[i][j];
        }
    }
}

// ---------------- layernorm over rows of length 512 ---------------------------
__global__ void ln_kernel(const float* __restrict__ X, float* __restrict__ Y,
                          const float* __restrict__ g, const float* __restrict__ b,
                          long ldx, long ldy)
{
    long row = blockIdx.x;
    const float* x = X + row * ldx;
    float* y = Y + row * ldy;
    int t = threadIdx.x;
    float v0 = x[t], v1 = x[t + 256];
    __shared__ float red[256];
    red[t] = v0 + v1; __syncthreads();
    for (int s = 128; s > 0; s >>= 1) { if (t < s) red[t] += red[t + s]; __syncthreads(); }
    float mu = red[0] * (1.f / 512.f); __syncthreads();
    float d0 = v0 - mu, d1 = v1 - mu;
    red[t] = d0 * d0 + d1 * d1; __syncthreads();
    for (int s = 128; s > 0; s >>= 1) { if (t < s) red[t] += red[t + s]; __syncthreads(); }
    float rstd = rsqrtf(red[0] * (1.f / 512.f) + 1e-5f);
    y[t] = d0 * rstd * g[t] + b[t];
    y[t + 256] = d1 * rstd * g[t + 256] + b[t + 256];
}

// ---------------- row softmax (block per row) ---------------------------------
__global__ void softmax_kernel(float* __restrict__ X, int L)
{
    long row = blockIdx.x;
    float* x = X + row * (long)L;
    int t = threadIdx.x;
    __shared__ float red[256];
    float mx = -1e30f;
    for (int i = t; i < L; i += 256) mx = fmaxf(mx, x[i]);
    red[t] = mx; __syncthreads();
    for (int s = 128; s > 0; s >>= 1) { if (t < s) red[t] = fmaxf(red[t], red[t + s]); __syncthreads(); }
    mx = red[0]; __syncthreads();
    float sum = 0.f;
    for (int i = t; i < L; i += 256) { float e = expf(x[i] - mx); x[i] = e; sum += e; }
    red[t] = sum; __syncthreads();
    for (int s = 128; s > 0; s >>= 1) { if (t < s) red[t] += red[t + s]; __syncthreads(); }
    float inv = 1.f / red[0];
    for (int i = t; i < L; i += 256) x[i] *= inv;
}

// ---------------- PPEG: sum of 7x7 + 5x5 + 3x3 depthwise convs + identity ----
__global__ void ppeg_kernel(const float* __restrict__ h0,
                            const float* __restrict__ k7, const float* __restrict__ b7,
                            const float* __restrict__ k5, const float* __restrict__ b5,
                            const float* __restrict__ k3, const float* __restrict__ b3,
                            float* __restrict__ hout)
{
    int pos = blockIdx.x, b = blockIdx.y, c = threadIdx.x;
    int y = pos >> 6, x = pos & 63;
    const float* base = h0 + ((long)b * N0) * CC + c;
    float acc = base[(long)pos * CC] + b7[c] + b5[c] + b3[c];
#pragma unroll
    for (int ky = 0; ky < 7; ky++) {
        int yy = y + ky - 3; if (yy < 0 || yy >= 64) continue;
#pragma unroll
        for (int kx = 0; kx < 7; kx++) {
            int xx = x + kx - 3; if (xx < 0 || xx >= 64) continue;
            acc += base[(long)(yy * 64 + xx) * CC] * k7[(c * 7 + ky) * 7 + kx];
        }
    }
#pragma unroll
    for (int ky = 0; ky < 5; ky++) {
        int yy = y + ky - 2; if (yy < 0 || yy >= 64) continue;
#pragma unroll
        for (int kx = 0; kx < 5; kx++) {
            int xx = x + kx - 2; if (xx < 0 || xx >= 64) continue;
            acc += base[(long)(yy * 64 + xx) * CC] * k5[(c * 5 + ky) * 5 + kx];
        }
    }
#pragma unroll
    for (int ky = 0; ky < 3; ky++) {
        int yy = y + ky - 1; if (yy < 0 || yy >= 64) continue;
#pragma unroll
        for (int kx = 0; kx < 3; kx++) {
            int xx = x + kx - 1; if (xx < 0 || xx >= 64) continue;
            acc += base[(long)(yy * 64 + xx) * CC] * k3[(c * 3 + ky) * 3 + kx];
        }
    }
    hout[((long)b * NC + 1 + pos) * CC + c] = acc;
}

__global__ void cls_kernel(const float* __restrict__ cls, float* __restrict__ h)
{
    h[(long)blockIdx.x * NC * CC + threadIdx.x] = cls[threadIdx.x];
}

// ---------------- qkv reorder: [b,tok,1536] -> [b,h,i,d] with front zero-pad --
__global__ void qkv_reorder_kernel(const float* __restrict__ qkv,
                                   float* __restrict__ q, float* __restrict__ k,
                                   float* __restrict__ v)
{
    int i = blockIdx.x, b = blockIdx.y, t = threadIdx.x;
    int h = t >> 6, d = t & 63;
    int tok = i - PADF;
    float qv = 0.f, kv = 0.f, vv = 0.f;
    if (tok >= 0) {
        const float* src = qkv + ((long)b * NC + tok) * 1536;
        qv = src[t]; kv = src[512 + t]; vv = src[1024 + t];
    }
    long dst = ((long)(b * NH + h) * NP + i) * DH + d;
    q[dst] = qv * 0.125f;   // DH^-0.5
    k[dst] = kv;
    v[dst] = vv;
}

// ---------------- landmark means: mean over l=17 consecutive tokens -----------
__global__ void landmark_kernel(const float* __restrict__ src, float* __restrict__ dst)
{
    int j = blockIdx.x, bh = blockIdx.y, d = threadIdx.x;
    const float* s = src + ((long)bh * NP + j * LLM) * DH + d;
    float acc = 0.f;
#pragma unroll
    for (int t = 0; t < LLM; t++) acc += s[t * DH];
    dst[((long)bh * MLM + j) * DH + d] = acc * (1.f / 17.f);
}

// ---------------- pinv helpers -------------------------------------------------
__global__ void reset_scal_kernel(float* s) { s[0] = 0.f; s[1] = 0.f; }

__global__ void colrow_max_kernel(const float* __restrict__ a2, float* s)
{
    int bz = blockIdx.x, t = threadIdx.x;
    const float* Mx = a2 + (long)bz * (MLM * MLM);
    float cs = 0.f, rs = 0.f;
    for (int i = 0; i < MLM; i++) cs += fabsf(Mx[i * MLM + t]);
    for (int j = 0; j < MLM; j++) rs += fabsf(Mx[t * MLM + j]);
    __shared__ float red[256];
    red[t] = rs; __syncthreads();
    for (int s2 = 128; s2 > 0; s2 >>= 1) { if (t < s2) red[t] = fmaxf(red[t], red[t + s2]); __syncthreads(); }
    if (t == 0) atomicMax((int*)&s[0], __float_as_int(red[0]));
    __syncthreads();
    red[t] = cs; __syncthreads();
    for (int s2 = 128; s2 > 0; s2 >>= 1) { if (t < s2) red[t] = fmaxf(red[t], red[t + s2]); __syncthreads(); }
    if (t == 0) atomicMax((int*)&s[1], __float_as_int(red[0]));
}

__global__ void pinv_init_kernel(const float* __restrict__ a2, float* __restrict__ z,
                                 const float* __restrict__ s)
{
    long idx = (long)blockIdx.x * 256 + threadIdx.x;
    float inv = 1.f / (s[0] * s[1]);
    long bz = idx >> 16;
    int r = (int)((idx >> 8) & 255), c = (int)(idx & 255);
    z[idx] = a2[(bz << 16) + ((long)c << 8) + r] * inv;
}

__global__ void aminus_kernel(const float* __restrict__ X, float* __restrict__ Y, float alpha)
{
    long idx = (long)blockIdx.x * 256 + threadIdx.x;
    int r = (int)((idx >> 8) & 255), c = (int)(idx & 255);
    Y[idx] = (r == c ? alpha : 0.f) - X[idx];
}

// ---------------- depthwise (33,1) residual conv over sequence ---------------
__global__ void resconv_kernel(const float* __restrict__ v, const float* __restrict__ rk,
                               float* __restrict__ out)
{
    int i = blockIdx.x, bh = blockIdx.y, d = threadIdx.x;
    int h = bh & 7;
    float acc = 0.f;
#pragma unroll
    for (int t = 0; t < 33; t++) {
        int ii = i + t - 16;
        if (ii >= 0 && ii < NP) acc += v[((long)bh * NP + ii) * DH + d] * rk[h * 33 + t];
    }
    out[((long)bh * NP + i) * DH + d] += acc;
}

// ---------------- [b,h,i,d] -> [b,tok,h*64+d], dropping the front pad ---------
__global__ void out_reorder_kernel(const float* __restrict__ ao, float* __restrict__ of)
{
    int tok = blockIdx.x, b = blockIdx.y, t = threadIdx.x;
    int h = t >> 6, d = t & 63;
    of[((long)b * NC + tok) * CC + t] =
        ao[((long)(b * NH + h) * NP + tok + PADF) * DH + d];
}

// =============================================================================
struct Ptrs {
    float *h0, *h, *xln, *qkvbuf, *q, *k, *v, *ql, *kl, *a1, *a3, *a2;
    float *z, *z2, *xz, *t, *av, *w, *ao, *oflat, *cls, *scal;
};

static void run_translayer(const Ptrs& P, const float* g, const float* bb,
                           const float* Wqkv, const float* Wout, const float* bout,
                           const float* rk)
{
    dim3 thr(16, 16);
    const long S2 = (long)MLM * MLM;
    ln_kernel<<<BB * NC, 256>>>(P.h, P.xln, g, bb, 512, 512);
    gemm_kernel<<<dim3(1536 / GT, (BB * NC + GT - 1) / GT), thr>>>(
        P.xln, Wqkv, P.qkvbuf, BB * NC, 1536, 512, nullptr, nullptr, 0);
    qkv_reorder_kernel<<<dim3(NP, BB), 512>>>(P.qkvbuf, P.q, P.k, P.v);
    landmark_kernel<<<dim3(MLM, BH), 64>>>(P.q, P.ql);
    landmark_kernel<<<dim3(MLM, BH), 64>>>(P.k, P.kl);
    // a2 = softmax(ql @ kl^T)
    bgemm_kernel<1><<<dim3(4, 4, BH), thr>>>(P.ql, P.kl, P.a2, MLM, MLM, DH,
                                             (long)MLM * DH, (long)MLM * DH, S2, 1.f);
    softmax_kernel<<<BH * MLM, 256>>>(P.a2, MLM);
    // a1 = softmax(q @ kl^T)
    bgemm_kernel<1><<<dim3(4, NP / GT, BH), thr>>>(P.q, P.kl, P.a1, NP, MLM, DH,
                                                   (long)NP * DH, (long)MLM * DH,
                                                   (long)NP * MLM, 1.f);
    softmax_kernel<<<BH * NP, 256>>>(P.a1, MLM);
    // a3 = softmax(ql @ k^T)
    bgemm_kernel<1><<<dim3(NP / GT, 4, BH), thr>>>(P.ql, P.k, P.a3, MLM, NP, DH,
                                                   (long)MLM * DH, (long)NP * DH,
                                                   (long)MLM * NP, 1.f);
    softmax_kernel<<<BH * MLM, 256>>>(P.a3, NP);
    // pinv(a2)
    reset_scal_kernel<<<1, 1>>>(P.scal);
    colrow_max_kernel<<<BH, 256>>>(P.a2, P.scal);
    pinv_init_kernel<<<BH * MLM, 256>>>(P.a2, P.z, P.scal);
    float* zc = P.z;
    float* zn = P.z2;
    for (int it = 0; it < 6; it++) {
        bgemm_kernel<0><<<dim3(4, 4, BH), thr>>>(P.a2, zc, P.xz, MLM, MLM, MLM, S2, S2, S2, 1.f);
        aminus_kernel<<<BH * MLM, 256>>>(P.xz, P.t, 7.f);
        bgemm_kernel<0><<<dim3(4, 4, BH), thr>>>(P.xz, P.t, zn, MLM, MLM, MLM, S2, S2, S2, 1.f);
        aminus_kernel<<<BH * MLM, 256>>>(zn, P.t, 15.f);
        bgemm_kernel<0><<<dim3(4, 4, BH), thr>>>(P.xz, P.t, zn, MLM, MLM, MLM, S2, S2, S2, 1.f);
        aminus_kernel<<<BH * MLM, 256>>>(zn, P.t, 13.f);
        bgemm_kernel<0><<<dim3(4, 4, BH), thr>>>(zc, P.t, zn, MLM, MLM, MLM, S2, S2, S2, 0.25f);
        float* tmp = zc; zc = zn; zn = tmp;
    }
    // av = a3 @ v
    bgemm_kernel<0><<<dim3(1, 4, BH), thr>>>(P.a3, P.v, P.av, MLM, DH, NP,
                                             (long)MLM * NP, (long)NP * DH, (long)MLM * DH, 1.f);
    // w = a1 @ z
    bgemm_kernel<0><<<dim3(4, NP / GT, BH), thr>>>(P.a1, zc, P.w, NP, MLM, MLM,
                                                   (long)NP * MLM, S2, (long)NP * MLM, 1.f);
    // ao = w @ av
    bgemm_kernel<0><<<dim3(1, NP / GT, BH), thr>>>(P.w, P.av, P.ao, NP, DH, MLM,
                                                   (long)NP * MLM, (long)MLM * DH, (long)NP * DH, 1.f);
    resconv_kernel<<<dim3(NP, BH), 64>>>(P.v, rk, P.ao);
    out_reorder_kernel<<<dim3(NC, BB), 512>>>(P.ao, P.oflat);
    // h = h + oflat @ Wout + bout   (in-place residual epilogue)
    gemm_kernel<<<dim3(512 / GT, (BB * NC + GT - 1) / GT), thr>>>(
        P.oflat, Wout, P.h, BB * NC, 512, 512, bout, P.h, 0);
}

extern "C" void kernel_launch(void* const* d_in, const int* in_sizes, int n_in,
                              void* d_out, int out_size)
{
    const float* x    = (const float*)d_in[0];
    const float* W1   = (const float*)d_in[1];
    const float* b1   = (const float*)d_in[2];
    const float* cls  = (const float*)d_in[3];
    const float* k7   = (const float*)d_in[4];
    const float* b7   = (const float*)d_in[5];
    const float* k5   = (const float*)d_in[6];
    const float* b5   = (const float*)d_in[7];
    const float* k3   = (const float*)d_in[8];
    const float* b3   = (const float*)d_in[9];
    const float* ln1g = (const float*)d_in[10];
    const float* ln1b = (const float*)d_in[11];
    const float* qkv1 = (const float*)d_in[12];
    const float* o1w  = (const float*)d_in[13];
    const float* o1b  = (const float*)d_in[14];
    const float* r1k  = (const float*)d_in[15];
    const float* ln2g = (const float*)d_in[16];
    const float* ln2b = (const float*)d_in[17];
    const float* qkv2 = (const float*)d_in[18];
    const float* o2w  = (const float*)d_in[19];
    const float* o2b  = (const float*)d_in[20];
    const float* r2k  = (const float*)d_in[21];
    const float* lnfg = (const float*)d_in[22];
    const float* lnfb = (const float*)d_in[23];
    const float* W2   = (const float*)d_in[24];
    const float* b2   = (const float*)d_in[25];
    float* out = (float*)d_out;

    Ptrs P;
    cudaGetSymbolAddress((void**)&P.h0, g_h0);
    cudaGetSymbolAddress((void**)&P.h, g_h);
    cudaGetSymbolAddress((void**)&P.xln, g_xln);
    cudaGetSymbolAddress((void**)&P.qkvbuf, g_qkvbuf);
    cudaGetSymbolAddress((void**)&P.q, g_q);
    cudaGetSymbolAddress((void**)&P.k, g_k);
    cudaGetSymbolAddress((void**)&P.v, g_v);
    cudaGetSymbolAddress((void**)&P.ql, g_ql);
    cudaGetSymbolAddress((void**)&P.kl, g_kl);
    cudaGetSymbolAddress((void**)&P.a1, g_a1);
    cudaGetSymbolAddress((void**)&P.a3, g_a3);
    cudaGetSymbolAddress((void**)&P.a2, g_a2);
    cudaGetSymbolAddress((void**)&P.z, g_z);
    cudaGetSymbolAddress((void**)&P.z2, g_z2);
    cudaGetSymbolAddress((void**)&P.xz, g_xz);
    cudaGetSymbolAddress((void**)&P.t, g_t);
    cudaGetSymbolAddress((void**)&P.av, g_av);
    cudaGetSymbolAddress((void**)&P.w, g_w);
    cudaGetSymbolAddress((void**)&P.ao, g_ao);
    cudaGetSymbolAddress((void**)&P.oflat, g_oflat);
    cudaGetSymbolAddress((void**)&P.cls, g_cls);
    cudaGetSymbolAddress((void**)&P.scal, g_scal);

    dim3 thr(16, 16);
    // fc1: h0 = relu(x @ W1 + b1)
    gemm_kernel<<<dim3(512 / GT, (BB * N0) / GT), thr>>>(
        x, W1, P.h0, BB * N0, 512, CIN, b1, nullptr, 1);
    // PPEG + cls concat
    ppeg_kernel<<<dim3(N0, BB), 512>>>(P.h0, k7, b7, k5, b5, k3, b3, P.h);
    cls_kernel<<<BB, 512>>>(cls, P.h);
    // two Nystrom transformer layers
    run_translayer(P, ln1g, ln1b, qkv1, o1w, o1b, r1k);
    run_translayer(P, ln2g, ln2b, qkv2, o2w, o2b, r2k);
    // final LN on token 0 only, then classifier
    ln_kernel<<<BB, 256>>>(P.h, P.cls, lnfg, lnfb, (long)NC * CC, CC);
    gemm_kernel<<<dim3((1000 + GT - 1) / GT, 1), thr>>>(
        P.cls, W2, out, BB, 1000, 512, b2, nullptr, 0);
}

// round 2
// speedup vs baseline: 2.0706x; 2.0706x over previous
#include <cuda_runtime.h>

#define BB 8
#define N0 4096
#define CIN 1024
#define CC 512
#define NC 4097
#define NP 4352
#define PADF 255
#define NH 8
#define DH 64
#define MLM 256
#define LLM 17
#define BH 64   /* BB*NH */

// ---------------- scratch (device globals; no allocations allowed) ------------
__device__ float g_h0[BB * N0 * CC];
__device__ float g_h[BB * NC * CC];
__device__ float g_xln[BB * NC * CC];
__device__ float g_qkvbuf[BB * NC * 3 * CC];
__device__ float g_q[BH * NP * DH];
__device__ float g_k[BH * NP * DH];
__device__ float g_v[BH * NP * DH];
__device__ float g_ql[BH * MLM * DH];
__device__ float g_kl[BH * MLM * DH];
__device__ float g_a1[BH * NP * MLM];
__device__ float g_a3[BH * MLM * NP];
__device__ float g_a2[BH * MLM * MLM];
__device__ float g_z[BH * MLM * MLM];
__device__ float g_z2[BH * MLM * MLM];
__device__ float g_xz[BH * MLM * MLM];
__device__ float g_t[BH * MLM * MLM];
__device__ float g_av[BH * MLM * DH];
__device__ float g_w[BH * NP * MLM];
__device__ float g_ao[BH * NP * DH];
__device__ float g_oflat[BB * NC * CC];
__device__ float g_cls[BB * CC];
__device__ float g_scal[2];

// =====================  TF32 tensor-core GEMM  ================================
// C[MxN] = alpha * A[MxK] @ op(B) (+bias)(+residual)(relu)
// TB=0: B is [K,N] (NN).  TB=1: B is [N,K] (C = A @ B^T).
// Block tile 128x128, K-tile 16, 8 warps (2x4) of 64x32, mma.m16n8k8.tf32.
#define Bb_M 128
#define Bb_N 128
#define Bb_K 16
#define SPAD 4

__device__ __forceinline__ unsigned f2tf(float x) {
    unsigned u; asm("cvt.rna.tf32.f32 %0, %1;" : "=r"(u) : "f"(x)); return u;
}
__device__ __forceinline__ void mma8(float* c, const unsigned* a, const unsigned* b) {
    asm volatile("mma.sync.aligned.m16n8k8.row.col.f32.tf32.tf32.f32 "
        "{%0,%1,%2,%3},{%4,%5,%6,%7},{%8,%9},{%0,%1,%2,%3};"
        : "+f"(c[0]), "+f"(c[1]), "+f"(c[2]), "+f"(c[3])
        : "r"(a[0]), "r"(a[1]), "r"(a[2]), "r"(a[3]), "r"(b[0]), "r"(b[1]));
}

template <int TB, bool BAT>
__global__ __launch_bounds__(256)
void tgemm(const float* __restrict__ A, const float* __restrict__ B,
           float* __restrict__ C, int M, int N, int K,
           long sA, long sB, long sC, float alpha,
           const float* __restrict__ bias, const float* __restrict__ residual,
           int relu)
{
    __shared__ unsigned As[2][Bb_K][Bb_M + SPAD];
    __shared__ unsigned Bs[2][Bb_K][Bb_N + SPAD];
    const float* Ab = BAT ? A + (long)blockIdx.z * sA : A;
    const float* Bb = BAT ? B + (long)blockIdx.z * sB : B;
    float* Cb = BAT ? C + (long)blockIdx.z * sC : C;

    const int tid = threadIdx.x;
    const int lane = tid & 31, warp = tid >> 5;
    const int gid = lane >> 2, tig = lane & 3;
    const int wm = (warp >> 2) * 64, wn = (warp & 3) * 32;
    const int row0 = blockIdx.y * Bb_M, col0 = blockIdx.x * Bb_N;

    float c[4][4][4];
#pragma unroll
    for (int i = 0; i < 4; i++)
#pragma unroll
        for (int j = 0; j < 4; j++)
#pragma unroll
            for (int l = 0; l < 4; l++) c[i][j][l] = 0.f;

    const int ntile = K / Bb_K;     // K % 16 == 0 for all call sites
    float ra[8], rb[8];

    // ---- load tile kt into registers ----
    auto ld_tile = [&](int kt) {
        const int k0 = kt * Bb_K;
#pragma unroll
        for (int i = 0; i < 2; i++) {          // A: 512 float4, 2/thread
            int v = tid + i * 256;
            int m = v >> 2, kq = v & 3;
            int gm = row0 + m;
            float4 f = make_float4(0.f, 0.f, 0.f, 0.f);
            if (gm < M) f = *(const float4*)&Ab[(long)gm * K + k0 + kq * 4];
            ra[i * 4 + 0] = f.x; ra[i * 4 + 1] = f.y;
            ra[i * 4 + 2] = f.z; ra[i * 4 + 3] = f.w;
        }
#pragma unroll
        for (int i = 0; i < 2; i++) {          // B: 512 float4, 2/thread
            int v = tid + i * 256;
            float4 f = make_float4(0.f, 0.f, 0.f, 0.f);
            if (TB) {
                int n = v >> 2, kq = v & 3;
                int gn = col0 + n;
                if (gn < N) f = *(const float4*)&Bb[(long)gn * K + k0 + kq * 4];
            } else {
                int kk = v >> 5, nq = v & 31;
                int gn = col0 + nq * 4;
                if (gn < N) f = *(const float4*)&Bb[(long)(k0 + kk) * N + gn];
            }
            rb[i * 4 + 0] = f.x; rb[i * 4 + 1] = f.y;
            rb[i * 4 + 2] = f.z; rb[i * 4 + 3] = f.w;
        }
    };
    auto st_tile = [&](int buf) {
#pragma unroll
        for (int i = 0; i < 2; i++) {
            int v = tid + i * 256;
            int m = v >> 2, kq = v & 3;
#pragma unroll
            for (int j = 0; j < 4; j++) As[buf][kq * 4 + j][m] = f2tf(ra[i * 4 + j]);
        }
#pragma unroll
        for (int i = 0; i < 2; i++) {
            int v = tid + i * 256;
            if (TB) {
                int n = v >> 2, kq = v & 3;
#pragma unroll
                for (int j = 0; j < 4; j++) Bs[buf][kq * 4 + j][n] = f2tf(rb[i * 4 + j]);
            } else {
                int kk = v >> 5, nq = v & 31;
                uint4 u;
                u.x = f2tf(rb[i * 4 + 0]); u.y = f2tf(rb[i * 4 + 1]);
                u.z = f2tf(rb[i * 4 + 2]); u.w = f2tf(rb[i * 4 + 3]);
                *(uint4*)&Bs[buf][kk][nq * 4] = u;
            }
        }
    };

    ld_tile(0);
    st_tile(0);
    __syncthreads();

    for (int kt = 0; kt < ntile; kt++) {
        const int buf = kt & 1;
        if (kt + 1 < ntile) ld_tile(kt + 1);
#pragma unroll
        for (int ks = 0; ks < 2; ks++) {
            const int kb = ks * 8;
            unsigned af[4][4], bf[4][2];
#pragma unroll
            for (int mt = 0; mt < 4; mt++) {
                int m0 = wm + mt * 16 + gid;
                af[mt][0] = As[buf][kb + tig][m0];
                af[mt][1] = As[buf][kb + tig][m0 + 8];
                af[mt][2] = As[buf][kb + tig + 4][m0];
                af[mt][3] = As[buf][kb + tig + 4][m0 + 8];
            }
#pragma unroll
            for (int nt = 0; nt < 4; nt++) {
                int n0 = wn + nt * 8 + gid;
                bf[nt][0] = Bs[buf][kb + tig][n0];
                bf[nt][1] = Bs[buf][kb + tig + 4][n0];
            }
#pragma unroll
            for (int mt = 0; mt < 4; mt++)
#pragma unroll
                for (int nt = 0; nt < 4; nt++) mma8(c[mt][nt], af[mt], bf[nt]);
        }
        if (kt + 1 < ntile) st_tile(buf ^ 1);
        __syncthreads();
    }

    // ---- epilogue ----
#pragma unroll
    for (int mt = 0; mt < 4; mt++) {
#pragma unroll
        for (int i = 0; i < 2; i++) {
            int r = row0 + wm + mt * 16 + gid + i * 8;
            if (r >= M) continue;
            float* crow = Cb + (long)r * N;
#pragma unroll
            for (int nt = 0; nt < 4; nt++) {
                int cc = col0 + wn + nt * 8 + 2 * tig;
                if (cc >= N) continue;
                float v0 = c[mt][nt][i * 2 + 0] * alpha;
                float v1 = c[mt][nt][i * 2 + 1] * alpha;
                if (bias) { v0 += bias[cc]; v1 += bias[cc + 1]; }
                if (residual) { v0 += crow == residual + (long)r * N ? 0.f : 0.f, v0 += residual[(long)r * N + cc], v1 += residual[(long)r * N + cc + 1]; }
                if (relu) { v0 = fmaxf(v0, 0.f); v1 = fmaxf(v1, 0.f); }
                crow[cc] = v0; crow[cc + 1] = v1;
            }
        }
    }
}

// ---------------- small SIMT GEMM (classifier only) ---------------------------
#define GT 64
#define GK 16
__global__ __launch_bounds__(256)
void gemm_kernel(const float* __restrict__ A, const float* __restrict__ B,
                 float* __restrict__ C, int M, int N, int K,
                 const float* __restrict__ bias)
{
    __shared__ float As[GK][GT + 1];
    __shared__ float Bsh[GK][GT + 1];
    int tx = threadIdx.x, ty = threadIdx.y;
    int tid = ty * 16 + tx;
    int row0 = blockIdx.y * GT;
    int col0 = blockIdx.x * GT;
    float acc[4][4] = {};
    for (int k0 = 0; k0 < K; k0 += GK) {
#pragma unroll
        for (int i = 0; i < 4; i++) {
            int idx = tid + i * 256;
            int m = idx >> 4, kk = idx & 15;
            int gm = row0 + m, gk = k0 + kk;
            As[kk][m] = (gm < M && gk < K) ? A[(long)gm * K + gk] : 0.f;
        }
#pragma unroll
        for (int i = 0; i < 4; i++) {
            int idx = tid + i * 256;
            int kk = idx >> 6, n = idx & 63;
            int gk = k0 + kk, gn = col0 + n;
            Bsh[kk][n] = (gk < K && gn < N) ? B[(long)gk * N + gn] : 0.f;
        }
        __syncthreads();
#pragma unroll
        for (int kk = 0; kk < GK; kk++) {
            float a[4], b[4];
#pragma unroll
            for (int i = 0; i < 4; i++) a[i] = As[kk][ty * 4 + i];
#pragma unroll
            for (int j = 0; j < 4; j++) b[j] = Bsh[kk][tx * 4 + j];
#pragma unroll
            for (int i = 0; i < 4; i++)
#pragma unroll
                for (int j = 0; j < 4; j++) acc[i][j] += a[i] * b[j];
        }
        __syncthreads();
    }
#pragma unroll
    for (int i = 0; i < 4; i++) {
        int gm = row0 + ty * 4 + i;
        if (gm >= M) continue;
#pragma unroll
        for (int j = 0; j < 4; j++) {
            int gn = col0 + tx * 4 + j;
            if (gn >= N) continue;
            float vv = acc[i][j];
            if (bias) vv += bias[gn];
            C[(long)gm * N + gn] = vv;
        }
    }
}

// ---------------- layernorm over rows of length 512 ---------------------------
__global__ void ln_kernel(const float* __restrict__ X, float* __restrict__ Y,
                          const float* __restrict__ g, const float* __restrict__ b,
                          long ldx, long ldy)
{
    long row = blockIdx.x;
    const float* x = X + row * ldx;
    float* y = Y + row * ldy;
    int t = threadIdx.x;
    float v0 = x[t], v1 = x[t + 256];
    __shared__ float red[256];
    red[t] = v0 + v1; __syncthreads();
    for (int s = 128; s > 0; s >>= 1) { if (t < s) red[t] += red[t + s]; __syncthreads(); }
    float mu = red[0] * (1.f / 512.f); __syncthreads();
    float d0 = v0 - mu, d1 = v1 - mu;
    red[t] = d0 * d0 + d1 * d1; __syncthreads();
    for (int s = 128; s > 0; s >>= 1) { if (t < s) red[t] += red[t + s]; __syncthreads(); }
    float rstd = rsqrtf(red[0] * (1.f / 512.f) + 1e-5f);
    y[t] = d0 * rstd * g[t] + b[t];
    y[t + 256] = d1 * rstd * g[t + 256] + b[t + 256];
}

// ---------------- row softmax (block per row) ---------------------------------
__global__ void softmax_kernel(float* __restrict__ X, int L)
{
    long row = blockIdx.x;
    float* x = X + row * (long)L;
    int t = threadIdx.x;
    __shared__ float red[256];
    float mx = -1e30f;
    for (int i = t; i < L; i += 256) mx = fmaxf(mx, x[i]);
    red[t] = mx; __syncthreads();
    for (int s = 128; s > 0; s >>= 1) { if (t < s) red[t] = fmaxf(red[t], red[t + s]); __syncthreads(); }
    mx = red[0]; __syncthreads();
    float sum = 0.f;
    for (int i = t; i < L; i += 256) { float e = expf(x[i] - mx); x[i] = e; sum += e; }
    red[t] = sum; __syncthreads();
    for (int s = 128; s > 0; s >>= 1) { if (t < s) red[t] += red[t + s]; __syncthreads(); }
    float inv = 1.f / red[0];
    for (int i = t; i < L; i += 256) x[i] *= inv;
}

// ---------------- PPEG: sum of 7x7 + 5x5 + 3x3 depthwise convs + identity ----
__global__ void ppeg_kernel(const float* __restrict__ h0,
                            const float* __restrict__ k7, const float* __restrict__ b7,
                            const float* __restrict__ k5, const float* __restrict__ b5,
                            const float* __restrict__ k3, const float* __restrict__ b3,
                            float* __restrict__ hout)
{
    int pos = blockIdx.x, b = blockIdx.y, c = threadIdx.x;
    int y = pos >> 6, x = pos & 63;
    const float* base = h0 + ((long)b * N0) * CC + c;
    float acc = base[(long)pos * CC] + b7[c] + b5[c] + b3[c];
#pragma unroll
    for (int ky = 0; ky < 7; ky++) {
        int yy = y + ky - 3; if (yy < 0 || yy >= 64) continue;
#pragma unroll
        for (int kx = 0; kx < 7; kx++) {
            int xx = x + kx - 3; if (xx < 0 || xx >= 64) continue;
            acc += base[(long)(yy * 64 + xx) * CC] * k7[(c * 7 + ky) * 7 + kx];
        }
    }
#pragma unroll
    for (int ky = 0; ky < 5; ky++) {
        int yy = y + ky - 2; if (yy < 0 || yy >= 64) continue;
#pragma unroll
        for (int kx = 0; kx < 5; kx++) {
            int xx = x + kx - 2; if (xx < 0 || xx >= 64) continue;
            acc += base[(long)(yy * 64 + xx) * CC] * k5[(c * 5 + ky) * 5 + kx];
        }
    }
#pragma unroll
    for (int ky = 0; ky < 3; ky++) {
        int yy = y + ky - 1; if (yy < 0 || yy >= 64) continue;
#pragma unroll
        for (int kx = 0; kx < 3; kx++) {
            int xx = x + kx - 1; if (xx < 0 || xx >= 64) continue;
            acc += base[(long)(yy * 64 + xx) * CC] * k3[(c * 3 + ky) * 3 + kx];
        }
    }
    hout[((long)b * NC + 1 + pos) * CC + c] = acc;
}

__global__ void cls_kernel(const float* __restrict__ cls, float* __restrict__ h)
{
    h[(long)blockIdx.x * NC * CC + threadIdx.x] = cls[threadIdx.x];
}

// ---------------- qkv reorder: [b,tok,1536] -> [b,h,i,d] with front zero-pad --
__global__ void qkv_reorder_kernel(const float* __restrict__ qkv,
                                   float* __restrict__ q, float* __restrict__ k,
                                   float* __restrict__ v)
{
    int i = blockIdx.x, b = blockIdx.y, t = threadIdx.x;
    int h = t >> 6, d = t & 63;
    int tok = i - PADF;
    float qv = 0.f, kv = 0.f, vv = 0.f;
    if (tok >= 0) {
        const float* src = qkv + ((long)b * NC + tok) * 1536;
        qv = src[t]; kv = src[512 + t]; vv = src[1024 + t];
    }
    long dst = ((long)(b * NH + h) * NP + i) * DH + d;
    q[dst] = qv * 0.125f;
    k[dst] = kv;
    v[dst] = vv;
}

// ---------------- landmark means -----------------------------------------------
__global__ void landmark_kernel(const float* __restrict__ src, float* __restrict__ dst)
{
    int j = blockIdx.x, bh = blockIdx.y, d = threadIdx.x;
    const float* s = src + ((long)bh * NP + j * LLM) * DH + d;
    float acc = 0.f;
#pragma unroll
    for (int t = 0; t < LLM; t++) acc += s[t * DH];
    dst[((long)bh * MLM + j) * DH + d] = acc * (1.f / 17.f);
}

// ---------------- pinv helpers -------------------------------------------------
__global__ void reset_scal_kernel(float* s) { s[0] = 0.f; s[1] = 0.f; }

__global__ void colrow_max_kernel(const float* __restrict__ a2, float* s)
{
    int bz = blockIdx.x, t = threadIdx.x;
    const float* Mx = a2 + (long)bz * (MLM * MLM);
    float cs = 0.f, rs = 0.f;
    for (int i = 0; i < MLM; i++) cs += fabsf(Mx[i * MLM + t]);
    for (int j = 0; j < MLM; j++) rs += fabsf(Mx[t * MLM + j]);
    __shared__ float red[256];
    red[t] = rs; __syncthreads();
    for (int s2 = 128; s2 > 0; s2 >>= 1) { if (t < s2) red[t] = fmaxf(red[t], red[t + s2]); __syncthreads(); }
    if (t == 0) atomicMax((int*)&s[0], __float_as_int(red[0]));
    __syncthreads();
    red[t] = cs; __syncthreads();
    for (int s2 = 128; s2 > 0; s2 >>= 1) { if (t < s2) red[t] = fmaxf(red[t], red[t + s2]); __syncthreads(); }
    if (t == 0) atomicMax((int*)&s[1], __float_as_int(red[0]));
}

__global__ void pinv_init_kernel(const float* __restrict__ a2, float* __restrict__ z,
                                 const float* __restrict__ s)
{
    long idx = (long)blockIdx.x * 256 + threadIdx.x;
    float inv = 1.f / (s[0] * s[1]);
    long bz = idx >> 16;
    int r = (int)((idx >> 8) & 255), c = (int)(idx & 255);
    z[idx] = a2[(bz << 16) + ((long)c << 8) + r] * inv;
}

__global__ void aminus_kernel(const float* __restrict__ X, float* __restrict__ Y, float alpha)
{
    long idx = (long)blockIdx.x * 256 + threadIdx.x;
    int r = (int)((idx >> 8) & 255), c = (int)(idx & 255);
    Y[idx] = (r == c ? alpha : 0.f) - X[idx];
}

// ---------------- depthwise (33,1) residual conv over sequence ---------------
__global__ void resconv_kernel(const float* __restrict__ v, const float* __restrict__ rk,
                               float* __restrict__ out)
{
    int i = blockIdx.x, bh = blockIdx.y, d = threadIdx.x;
    int h = bh & 7;
    float acc = 0.f;
#pragma unroll
    for (int t = 0; t < 33; t++) {
        int ii = i + t - 16;
        if (ii >= 0 && ii < NP) acc += v[((long)bh * NP + ii) * DH + d] * rk[h * 33 + t];
    }
    out[((long)bh * NP + i) * DH + d] += acc;
}

// ---------------- [b,h,i,d] -> [b,tok,h*64+d], dropping the front pad ---------
__global__ void out_reorder_kernel(const float* __restrict__ ao, float* __restrict__ of)
{
    int tok = blockIdx.x, b = blockIdx.y, t = threadIdx.x;
    int h = t >> 6, d = t & 63;
    of[((long)b * NC + tok) * CC + t] =
        ao[((long)(b * NH + h) * NP + tok + PADF) * DH + d];
}

// =============================================================================
struct Ptrs {
    float *h0, *h, *xln, *qkvbuf, *q, *k, *v, *ql, *kl, *a1, *a3, *a2;
    float *z, *z2, *xz, *t, *av, *w, *ao, *oflat, *cls, *scal;
};

static inline dim3 ggrid(int M, int N, int Z) {
    return dim3((N + Bb_N - 1) / Bb_N, (M + Bb_M - 1) / Bb_M, Z);
}

static void run_translayer(const Ptrs& P, const float* g, const float* bb,
                           const float* Wqkv, const float* Wout, const float* bout,
                           const float* rk)
{
    const long S2 = (long)MLM * MLM;
    ln_kernel<<<BB * NC, 256>>>(P.h, P.xln, g, bb, 512, 512);
    tgemm<0, false><<<ggrid(BB * NC, 1536, 1), 256>>>(
        P.xln, Wqkv, P.qkvbuf, BB * NC, 1536, 512, 0, 0, 0, 1.f, nullptr, nullptr, 0);
    qkv_reorder_kernel<<<dim3(NP, BB), 512>>>(P.qkvbuf, P.q, P.k, P.v);
    landmark_kernel<<<dim3(MLM, BH), 64>>>(P.q, P.ql);
    landmark_kernel<<<dim3(MLM, BH), 64>>>(P.k, P.kl);
    // a2 = softmax(ql @ kl^T)
    tgemm<1, true><<<ggrid(MLM, MLM, BH), 256>>>(
        P.ql, P.kl, P.a2, MLM, MLM, DH, (long)MLM * DH, (long)MLM * DH, S2, 1.f,
        nullptr, nullptr, 0);
    softmax_kernel<<<BH * MLM, 256>>>(P.a2, MLM);
    // a1 = softmax(q @ kl^T)
    tgemm<1, true><<<ggrid(NP, MLM, BH), 256>>>(
        P.q, P.kl, P.a1, NP, MLM, DH, (long)NP * DH, (long)MLM * DH, (long)NP * MLM,
        1.f, nullptr, nullptr, 0);
    softmax_kernel<<<BH * NP, 256>>>(P.a1, MLM);
    // a3 = softmax(ql @ k^T)
    tgemm<1, true><<<ggrid(MLM, NP, BH), 256>>>(
        P.ql, P.k, P.a3, MLM, NP, DH, (long)MLM * DH, (long)NP * DH, (long)MLM * NP,
        1.f, nullptr, nullptr, 0);
    softmax_kernel<<<BH * MLM, 256>>>(P.a3, NP);
    // pinv(a2)
    reset_scal_kernel<<<1, 1>>>(P.scal);
    colrow_max_kernel<<<BH, 256>>>(P.a2, P.scal);
    pinv_init_kernel<<<BH * MLM, 256>>>(P.a2, P.z, P.scal);
    float* zc = P.z;
    float* zn = P.z2;
    for (int it = 0; it < 6; it++) {
        tgemm<0, true><<<ggrid(MLM, MLM, BH), 256>>>(
            P.a2, zc, P.xz, MLM, MLM, MLM, S2, S2, S2, 1.f, nullptr, nullptr, 0);
        aminus_kernel<<<BH * MLM, 256>>>(P.xz, P.t, 7.f);
        tgemm<0, true><<<ggrid(MLM, MLM, BH), 256>>>(
            P.xz, P.t, zn, MLM, MLM, MLM, S2, S2, S2, 1.f, nullptr, nullptr, 0);
        aminus_kernel<<<BH * MLM, 256>>>(zn, P.t, 15.f);
        tgemm<0, true><<<ggrid(MLM, MLM, BH), 256>>>(
            P.xz, P.t, zn, MLM, MLM, MLM, S2, S2, S2, 1.f, nullptr, nullptr, 0);
        aminus_kernel<<<BH * MLM, 256>>>(zn, P.t, 13.f);
        tgemm<0, true><<<ggrid(MLM, MLM, BH), 256>>>(
            zc, P.t, zn, MLM, MLM, MLM, S2, S2, S2, 0.25f, nullptr, nullptr, 0);
        float* tmp = zc; zc = zn; zn = tmp;
    }
    // av = a3 @ v
    tgemm<0, true><<<ggrid(MLM, DH, BH), 256>>>(
        P.a3, P.v, P.av, MLM, DH, NP, (long)MLM * NP, (long)NP * DH, (long)MLM * DH,
        1.f, nullptr, nullptr, 0);
    // w = a1 @ z
    tgemm<0, true><<<ggrid(NP, MLM, BH), 256>>>(
        P.a1, zc, P.w, NP, MLM, MLM, (long)NP * MLM, S2, (long)NP * MLM, 1.f,
        nullptr, nullptr, 0);
    // ao = w @ av
    tgemm<0, true><<<ggrid(NP, DH, BH), 256>>>(
        P.w, P.av, P.ao, NP, DH, MLM, (long)NP * MLM, (long)MLM * DH, (long)NP * DH,
        1.f, nullptr, nullptr, 0);
    resconv_kernel<<<dim3(NP, BH), 64>>>(P.v, rk, P.ao);
    out_reorder_kernel<<<dim3(NC, BB), 512>>>(P.ao, P.oflat);
    // h = h + oflat @ Wout + bout
    tgemm<0, false><<<ggrid(BB * NC, 512, 1), 256>>>(
        P.oflat, Wout, P.h, BB * NC, 512, 512, 0, 0, 0, 1.f, bout, P.h, 0);
}

extern "C" void kernel_launch(void* const* d_in, const int* in_sizes, int n_in,
                              void* d_out, int out_size)
{
    const float* x    = (const float*)d_in[0];
    const float* W1   = (const float*)d_in[1];
    const float* b1   = (const float*)d_in[2];
    const float* cls  = (const float*)d_in[3];
    const float* k7   = (const float*)d_in[4];
    const float* b7   = (const float*)d_in[5];
    const float* k5   = (const float*)d_in[6];
    const float* b5   = (const float*)d_in[7];
    const float* k3   = (const float*)d_in[8];
    const float* b3   = (const float*)d_in[9];
    const float* ln1g = (const float*)d_in[10];
    const float* ln1b = (const float*)d_in[11];
    const float* qkv1 = (const float*)d_in[12];
    const float* o1w  = (const float*)d_in[13];
    const float* o1b  = (const float*)d_in[14];
    const float* r1k  = (const float*)d_in[15];
    const float* ln2g = (const float*)d_in[16];
    const float* ln2b = (const float*)d_in[17];
    const float* qkv2 = (const float*)d_in[18];
    const float* o2w  = (const float*)d_in[19];
    const float* o2b  = (const float*)d_in[20];
    const float* r2k  = (const float*)d_in[21];
    const float* lnfg = (const float*)d_in[22];
    const float* lnfb = (const float*)d_in[23];
    const float* W2   = (const float*)d_in[24];
    const float* b2   = (const float*)d_in[25];
    float* out = (float*)d_out;

    Ptrs P;
    cudaGetSymbolAddress((void**)&P.h0, g_h0);
    cudaGetSymbolAddress((void**)&P.h, g_h);
    cudaGetSymbolAddress((void**)&P.xln, g_xln);
    cudaGetSymbolAddress((void**)&P.qkvbuf, g_qkvbuf);
    cudaGetSymbolAddress((void**)&P.q, g_q);
    cudaGetSymbolAddress((void**)&P.k, g_k);
    cudaGetSymbolAddress((void**)&P.v, g_v);
    cudaGetSymbolAddress((void**)&P.ql, g_ql);
    cudaGetSymbolAddress((void**)&P.kl, g_kl);
    cudaGetSymbolAddress((void**)&P.a1, g_a1);
    cudaGetSymbolAddress((void**)&P.a3, g_a3);
    cudaGetSymbolAddress((void**)&P.a2, g_a2);
    cudaGetSymbolAddress((void**)&P.z, g_z);
    cudaGetSymbolAddress((void**)&P.z2, g_z2);
    cudaGetSymbolAddress((void**)&P.xz, g_xz);
    cudaGetSymbolAddress((void**)&P.t, g_t);
    cudaGetSymbolAddress((void**)&P.av, g_av);
    cudaGetSymbolAddress((void**)&P.w, g_w);
    cudaGetSymbolAddress((void**)&P.ao, g_ao);
    cudaGetSymbolAddress((void**)&P.oflat, g_oflat);
    cudaGetSymbolAddress((void**)&P.cls, g_cls);
    cudaGetSymbolAddress((void**)&P.scal, g_scal);

    // fc1: h0 = relu(x @ W1 + b1)
    tgemm<0, false><<<ggrid(BB * N0, 512, 1), 256>>>(
        x, W1, P.h0, BB * N0, 512, CIN, 0, 0, 0, 1.f, b1, nullptr, 1);
    // PPEG + cls concat
    ppeg_kernel<<<dim3(N0, BB), 512>>>(P.h0, k7, b7, k5, b5, k3, b3, P.h);
    cls_kernel<<<BB, 512>>>(cls, P.h);
    // two Nystrom transformer layers
    run_translayer(P, ln1g, ln1b, qkv1, o1w, o1b, r1k);
    run_translayer(P, ln2g, ln2b, qkv2, o2w, o2b, r2k);
    // final LN on token 0 only, then classifier
    ln_kernel<<<BB, 256>>>(P.h, P.cls, lnfg, lnfb, (long)NC * CC, CC);
    dim3 thr(16, 16);
    gemm_kernel<<<dim3((1000 + GT - 1) / GT, 1), thr>>>(
        P.cls, W2, out, BB, 1000, 512, b2);
}